// round 13
// baseline (speedup 1.0000x reference)
#include <cuda_runtime.h>
#include <cstdint>

#define NGRP   1024          // CTAs, 4 batches each
#define B_PER  4
#define T_TOT  512
#define XT     32            // timesteps per x-slot
#define NIT    16            // iterations = T/XT
#define XS     2             // x-slots
#define RT     8             // timesteps per ring chunk
#define NCH    64            // ring chunks
#define NTHREADS 96          // w0: gates L1, w1: gates L2, w2: consumer(l<8) + TMA(l==31)

#define ROW_STRIDE_B (T_TOT * 25 * 4)      // 51200 B per batch row
#define XROW4       202                    // f4 per xbuf row (800 + 8 pad) -> lane-distinct banks
#define XROW_B      (XROW4 * 16)           // 3232
#define XSLOT_F4    (B_PER * XROW4)        // 808
#define XSLOT_B     (B_PER * XROW_B)       // 12928
#define TILE_ROW_B  3200                   // bytes per row per slot
#define TILE_B      (B_PER * TILE_ROW_B)   // 12800
#define RING_TS     36                     // ring floats per timestep (bank spread)
#define RING_FLOATS (4 * RT * RING_TS)     // 1152 floats
#define SMEM_BYTES  (RING_FLOATS * 4 + XS * XSLOT_B)   // ~30.5 KB

__device__ __forceinline__ float tanha(float v) {
    float y;
    asm("tanh.approx.f32 %0, %1;" : "=f"(y) : "f"(v));
    return y;
}

__device__ __forceinline__ uint32_t smem_u32(const void* p) {
    uint32_t a;
    asm("{ .reg .u64 t; cvta.to.shared.u64 t, %1; cvt.u32.u64 %0, t; }" : "=r"(a) : "l"(p));
    return a;
}

#define MBAR_INIT(addr, cnt) \
    asm volatile("mbarrier.init.shared.b64 [%0], %1;" :: "r"(addr), "r"(cnt) : "memory")
#define MBAR_ARRIVE(addr) \
    asm volatile("mbarrier.arrive.release.cta.shared::cta.b64 _, [%0];" :: "r"(addr) : "memory")
#define MBAR_EXPECT_TX(addr, bytes) \
    asm volatile("mbarrier.arrive.expect_tx.shared.b64 _, [%0], %1;" \
                 :: "r"(addr), "r"(bytes) : "memory")
#define CP_BULK(dst_u32, src_ptr, bytes, mbar) \
    asm volatile("cp.async.bulk.shared::cta.global.mbarrier::complete_tx::bytes [%0], [%1], %2, [%3];" \
                 :: "r"(dst_u32), "l"(src_ptr), "r"(bytes), "r"(mbar) : "memory")

__device__ __forceinline__ void mbar_wait_parity(uint32_t mbar, uint32_t parity) {
    uint32_t done;
    asm volatile(
        "{\n\t.reg .pred p;\n\t"
        "mbarrier.try_wait.parity.acquire.cta.shared::cta.b64 p, [%1], %2;\n\t"
        "selp.b32 %0, 1, 0, p;\n\t}"
        : "=r"(done) : "r"(mbar), "r"(parity) : "memory");
    if (!done) {
        asm volatile(
            "{\n\t.reg .pred P1;\n\t"
            "W_%=:\n\t"
            "mbarrier.try_wait.parity.acquire.cta.shared::cta.b64 P1, [%0], %1, 0x989680;\n\t"
            "@P1 bra.uni D_%=;\n\t"
            "bra.uni W_%=;\n\t"
            "D_%=:\n\t}"
            :: "r"(mbar), "r"(parity) : "memory");
    }
}

// bars[] byte offsets: XFULL[2], XEMPTY[2], RFULL[4], REMPTY[4]
#define XFULL(s)  ((s) * 8)
#define XEMPTY(s) ((2 + (s)) * 8)
#define RFULL(s)  ((4 + (s)) * 8)
#define REMPTY(s) ((8 + (s)) * 8)

// ---------------------------------------------------------------------------
// Gate warp (one per LSTM): lane = (tq<<2)|b. Thread computes timesteps
// t = tq*4+i (i=0..3) of the 32-t slot for batch b: offset==i compile-time.
// XROW4=202 -> bank = (8b + 4tq + c) mod 32, lane-distinct per phase.
// ---------------------------------------------------------------------------
template <int NF>
__device__ __forceinline__ void gate_loop(
    const float4* __restrict__ xb4, float* __restrict__ ring, uint32_t bar,
    int l, const float* __restrict__ Wih, const float* __restrict__ bp)
{
    constexpr int FOFF = (NF == 13) ? 12 : 0;
    constexpr int LOFF = (NF == 13) ? 16 : 0;

    float w[4][13], bb[4];
    #pragma unroll
    for (int g = 0; g < 4; g++) {
        float sc = (g == 2) ? 1.0f : 0.5f;
        bb[g] = bp[g] * sc;
        #pragma unroll
        for (int f = 0; f < NF; f++) w[g][f] = Wih[g * NF + f] * sc;
    }

    const int b  = l & 3;
    const int tq = l >> 2;            // 0..7
    const int rslot = tq >> 1;        // 0..3

    for (int it = 0; it < NIT; it++) {
        const int xs = it & 1;
        mbar_wait_parity(bar + XFULL(xs), (uint32_t)((it >> 1) & 1));   // x-slot landed
        mbar_wait_parity(bar + REMPTY(rslot), 1u ^ (it & 1));           // ring slot free

        const float4* xr = xb4 + (size_t)xs * XSLOT_F4 + (size_t)b * XROW4;

        #pragma unroll
        for (int i = 0; i < 4; i++) {
            const int tloc = tq * 4 + i;
            const int q0 = (tloc * 25 + FOFF) >> 2;     // window start; offset == i
            const int nq = (i + NF + 3) >> 2;

            float xa[16];
            #pragma unroll
            for (int j = 0; j < 4; j++) {
                if (j < nq) {
                    float4 t = xr[q0 + j];
                    xa[4 * j + 0] = t.x; xa[4 * j + 1] = t.y;
                    xa[4 * j + 2] = t.z; xa[4 * j + 3] = t.w;
                }
            }

            float a0 = bb[0], a1 = bb[1], a2 = bb[2], a3 = bb[3];
            #pragma unroll
            for (int f = 0; f < NF; f++) {
                float v = xa[i + f];
                a0 = fmaf(w[0][f], v, a0);
                a1 = fmaf(w[1][f], v, a1);
                a2 = fmaf(w[2][f], v, a2);
                a3 = fmaf(w[3][f], v, a3);
            }

            *(float4*)(ring + (size_t)(rslot * RT + (tloc & 7)) * RING_TS + LOFF + b * 4) =
                make_float4(a0, a1, a2, a3);
        }

        __syncwarp();
        if (l == 0) {
            MBAR_ARRIVE(bar + XEMPTY(xs));      // count 2 (both gate warps)
            MBAR_ARRIVE(bar + RFULL(0));
            MBAR_ARRIVE(bar + RFULL(1));
            MBAR_ARRIVE(bar + RFULL(2));
            MBAR_ARRIVE(bar + RFULL(3));
        }
    }
}

// ---------------------------------------------------------------------------
__global__ __launch_bounds__(NTHREADS, 7) void fused_kernel(
    const float* __restrict__ x,
    const float* __restrict__ Wih1, const float* __restrict__ Whh1, const float* __restrict__ b1,
    const float* __restrict__ Wih2, const float* __restrict__ Whh2, const float* __restrict__ b2,
    const float* __restrict__ Wout, const float* __restrict__ bout,
    float* __restrict__ out)
{
    extern __shared__ float smem[];
    float* ring = smem;                              // [4][RT][RING_TS]
    char*  xbuf = (char*)(smem + RING_FLOATS);       // [XS][B_PER][XROW_B]

    __shared__ __align__(8) uint64_t bars[12];

    const int tid = threadIdx.x;
    const int wid = tid >> 5;
    const int l   = tid & 31;
    const int bg  = blockIdx.x;

    const uint32_t bar = smem_u32(bars);

    if (tid == 0) {
        #pragma unroll
        for (int s = 0; s < XS; s++) {
            MBAR_INIT(bar + XFULL(s),  1);   // tx-based
            MBAR_INIT(bar + XEMPTY(s), 2);   // 2 gate warps (elected)
        }
        #pragma unroll
        for (int s = 0; s < 4; s++) {
            MBAR_INIT(bar + RFULL(s),  2);   // 2 gate warps
            MBAR_INIT(bar + REMPTY(s), 1);   // consumer lane 0
        }
    }
    __syncthreads();

    if (wid == 0) {
        gate_loop<12>((const float4*)xbuf, ring, bar, l, Wih1, b1);
    } else if (wid == 1) {
        gate_loop<13>((const float4*)xbuf, ring, bar, l, Wih2, b2);
    } else if (l < 8) {
        // ===== CONSUMER: lanes 0-7 = (L = l>>2, b = l&3) =====================
        const int L = l >> 2;
        const int b = l & 3;

        const float* Whh = L ? Whh2 : Whh1;
        const float whi = Whh[0] * 0.5f;
        const float whf = Whh[1] * 0.5f;
        const float whg = Whh[2];
        const float who = Whh[3] * 0.5f;

        float h = 0.0f, c = 0.0f;

        for (int j = 0; j < NCH; j++) {
            const int s = j & 3;
            mbar_wait_parity(bar + RFULL(s), (uint32_t)((j >> 2) & 1));

            const float* zb = ring + (size_t)(s * RT) * RING_TS + L * 16 + b * 4;
            float4 z = *(const float4*)zb;
            #pragma unroll
            for (int d = 0; d < RT; d++) {
                float4 zn = z;
                if (d + 1 < RT) zn = *(const float4*)(zb + (d + 1) * RING_TS);

                float zi = fmaf(whi, h, z.x);
                float zf = fmaf(whf, h, z.y);
                float zg = fmaf(whg, h, z.z);
                float zo = fmaf(who, h, z.w);

                float gi = fmaf(0.5f, tanha(zi), 0.5f);
                float gf = fmaf(0.5f, tanha(zf), 0.5f);
                float gg = tanha(zg);
                float go = fmaf(0.5f, tanha(zo), 0.5f);

                c = fmaf(gf, c, gi * gg);
                h = go * tanha(c);
                z = zn;
            }
            __syncwarp(0x000000ffu);
            if (l == 0) MBAR_ARRIVE(bar + REMPTY(s));
        }

        float h2 = __shfl_sync(0x000000ffu, h, l + 4);
        if (l < 4) {
            float y = fmaf(Wout[0], h, fmaf(Wout[1], h2, bout[0]));
            out[bg * B_PER + b] = 1.0f / (1.0f + __expf(-y));
        }
    } else if (l == 31) {
        // ===== TMA CONTROL: single lane, 3200B bulk copies ===================
        const char* xsrc = (const char*)x + (size_t)bg * B_PER * ROW_STRIDE_B;
        const uint32_t xb_base = smem_u32(xbuf);

        int es = 0, ep = 0;
        for (int xt = 0; xt < NIT; xt++) {
            const int slot = xt & 1;
            if (xt >= XS) {
                mbar_wait_parity(bar + XEMPTY(es), (uint32_t)ep);
                if (++es == XS) { es = 0; ep ^= 1; }
            }
            MBAR_EXPECT_TX(bar + XFULL(slot), TILE_B);
            const uint32_t dslot = xb_base + (uint32_t)slot * XSLOT_B;
            const char* src = xsrc + (size_t)xt * TILE_ROW_B;
            #pragma unroll
            for (int b = 0; b < B_PER; b++) {
                CP_BULK(dslot + (uint32_t)b * XROW_B,
                        src + (size_t)b * ROW_STRIDE_B,
                        TILE_ROW_B, bar + XFULL(slot));
            }
        }
    }
}

// ---------------------------------------------------------------------------
extern "C" void kernel_launch(void* const* d_in, const int* in_sizes, int n_in,
                              void* d_out, int out_size)
{
    const float* x    = (const float*)d_in[0];
    const float* Wih1 = (const float*)d_in[1];
    const float* Whh1 = (const float*)d_in[2];
    const float* b1   = (const float*)d_in[3];
    const float* Wih2 = (const float*)d_in[4];
    const float* Whh2 = (const float*)d_in[5];
    const float* b2   = (const float*)d_in[6];
    const float* Wout = (const float*)d_in[7];
    const float* bout = (const float*)d_in[8];

    cudaFuncSetAttribute(fused_kernel, cudaFuncAttributeMaxDynamicSharedMemorySize, SMEM_BYTES);
    fused_kernel<<<NGRP, NTHREADS, SMEM_BYTES>>>(
        x, Wih1, Whh1, b1, Wih2, Whh2, b2, Wout, bout, (float*)d_out);
}

// round 14
// speedup vs baseline: 1.9346x; 1.9346x over previous
#include <cuda_runtime.h>
#include <cstdint>

#define NGRP    128
#define T_TOT   512
#define TILE_T  16
#define NTILE   32
#define XS      3            // shared x-slots (even: cp.async, odd: TMA)
#define RS      2            // gate-ring slots
#define NTHREADS 608         // 8 stage + 8 gate + 2 consumer + 1 TMA warps

#define ROW_STRIDE_B (T_TOT * 25 * 4)        // 51200 B per batch row
#define XROW4       101                      // f4 per xbuf row (odd stride -> conflict-free LDS)
#define XROW_B      (XROW4 * 16)             // 1616
#define TILE_ROW_B  1600                     // bytes per row per 16-t tile
#define XSLOT_F4    (32 * XROW4)             // 3232
#define XSLOT_B     (XSLOT_F4 * 16)          // 51712
#define TILE_B      (32 * TILE_ROW_B)        // 51200
#define RING_FLOATS (RS * TILE_T * 256)      // 8192 floats = 32 KB
#define SMEM_BYTES  (RING_FLOATS * 4 + XS * XSLOT_B)   // 187904 B

__device__ __forceinline__ float tanha(float v) {
    float y;
    asm("tanh.approx.f32 %0, %1;" : "=f"(y) : "f"(v));
    return y;
}

__device__ __forceinline__ uint32_t smem_u32(const void* p) {
    uint32_t a;
    asm("{ .reg .u64 t; cvta.to.shared.u64 t, %1; cvt.u32.u64 %0, t; }" : "=r"(a) : "l"(p));
    return a;
}

#define MBAR_INIT(addr, cnt) \
    asm volatile("mbarrier.init.shared.b64 [%0], %1;" :: "r"(addr), "r"(cnt) : "memory")
#define MBAR_ARRIVE(addr) \
    asm volatile("mbarrier.arrive.release.cta.shared::cta.b64 _, [%0];" :: "r"(addr) : "memory")
#define MBAR_EXPECT_TX(addr, bytes) \
    asm volatile("mbarrier.arrive.expect_tx.shared.b64 _, [%0], %1;" \
                 :: "r"(addr), "r"(bytes) : "memory")
#define CP_BULK(dst_u32, src_ptr, bytes, mbar) \
    asm volatile("cp.async.bulk.shared::cta.global.mbarrier::complete_tx::bytes [%0], [%1], %2, [%3];" \
                 :: "r"(dst_u32), "l"(src_ptr), "r"(bytes), "r"(mbar) : "memory")

__device__ __forceinline__ void mbar_wait_parity(uint32_t mbar, uint32_t parity) {
    uint32_t done;
    asm volatile(
        "{\n\t.reg .pred p;\n\t"
        "mbarrier.try_wait.parity.acquire.cta.shared::cta.b64 p, [%1], %2;\n\t"
        "selp.b32 %0, 1, 0, p;\n\t}"
        : "=r"(done) : "r"(mbar), "r"(parity) : "memory");
    if (!done) {
        asm volatile(
            "{\n\t.reg .pred P1;\n\t"
            "W_%=:\n\t"
            "mbarrier.try_wait.parity.acquire.cta.shared::cta.b64 P1, [%0], %1, 0x989680;\n\t"
            "@P1 bra.uni D_%=;\n\t"
            "bra.uni W_%=;\n\t"
            "D_%=:\n\t}"
            :: "r"(mbar), "r"(parity) : "memory");
    }
}

#define CP_ASYNC16(dst_u32, src_ptr) \
    asm volatile("cp.async.cg.shared.global [%0], [%1], 16;" \
                 :: "r"(dst_u32), "l"(src_ptr) : "memory")
#define CP_COMMIT()  asm volatile("cp.async.commit_group;" ::: "memory")
#define CP_WAIT(N)   asm volatile("cp.async.wait_group %0;" :: "n"(N) : "memory")

// bar id 1/2 join the 256 stage + 256 gate threads (count 512)
#define BAR_SYNC(id)   asm volatile("bar.sync %0, 512;"   :: "n"(id) : "memory")
#define BAR_ARRIVE(id) asm volatile("bar.arrive %0, 512;" :: "n"(id) : "memory")

// bars[] byte offsets: XFULL[3], XEMPTY(single), RFULL[2], REMPTY[2]
#define XFULL(s)  ((s) * 8)
#define XEMPTY    (3 * 8)
#define RFULL(s)  ((4 + (s)) * 8)
#define REMPTY(s) ((6 + (s)) * 8)

// ---------------------------------------------------------------------------
// Gate warps: one warp per (LSTM L, t-quad tq). lane = batch.
// Even tiles arrive via bar(1) from stage warps; odd tiles via XFULL mbars.
// ---------------------------------------------------------------------------
template <int NF>
__device__ __forceinline__ void gate_loop(
    const float4* __restrict__ xb4, float* __restrict__ ring, uint32_t bar,
    int l, int tq, const float* __restrict__ Wih, const float* __restrict__ bp)
{
    constexpr int FOFF = (NF == 13) ? 12 : 0;
    constexpr int LOFF = (NF == 13) ? 128 : 0;

    float w[4][13], bb[4];
    #pragma unroll
    for (int g = 0; g < 4; g++) {
        float sc = (g == 2) ? 1.0f : 0.5f;
        bb[g] = bp[g] * sc;
        #pragma unroll
        for (int f = 0; f < NF; f++) w[g][f] = Wih[g * NF + f] * sc;
    }

    const int tq4 = tq * 4;

    for (int k = 0; k < NTILE; k++) {
        const int slot = k % 3;
        if ((k & 1) == 0) {
            BAR_SYNC(1);                                       // stage signals even tile k
        } else {
            mbar_wait_parity(bar + XFULL(slot), (uint32_t)(((k - 1) / 6) & 1));  // TMA tx
        }
        const int s = k & 1;
        mbar_wait_parity(bar + REMPTY(s), 1u ^ ((k >> 1) & 1));   // ring slot free

        const float4* xr = xb4 + (size_t)slot * XSLOT_F4 + (size_t)l * XROW4;

        #pragma unroll
        for (int i = 0; i < 4; i++) {
            const int tloc = tq4 + i;
            const int q0 = (tloc * 25 + FOFF) >> 2;   // window start; offset == i
            const int nq = (i + NF + 3) >> 2;

            float xa[16];
            #pragma unroll
            for (int j = 0; j < 4; j++) {
                if (j < nq) {
                    float4 t = xr[q0 + j];
                    xa[4 * j + 0] = t.x; xa[4 * j + 1] = t.y;
                    xa[4 * j + 2] = t.z; xa[4 * j + 3] = t.w;
                }
            }

            float a0 = bb[0], a1 = bb[1], a2 = bb[2], a3 = bb[3];
            #pragma unroll
            for (int f = 0; f < NF; f++) {
                float v = xa[i + f];
                a0 = fmaf(w[0][f], v, a0);
                a1 = fmaf(w[1][f], v, a1);
                a2 = fmaf(w[2][f], v, a2);
                a3 = fmaf(w[3][f], v, a3);
            }

            *(float4*)(ring + (size_t)(s * TILE_T + tloc) * 256 + LOFF + l * 4) =
                make_float4(a0, a1, a2, a3);
        }

        __syncwarp();
        if (l == 0) MBAR_ARRIVE(bar + RFULL(s));     // ring slot filled (count 8)

        // slot-free credit routes to the slot's NEXT user (tile k+3, opposite parity)
        if ((k & 1) == 0) {
            if (k <= 28 && l == 0) MBAR_ARRIVE(bar + XEMPTY);    // credit TMA (count 8)
        } else if (k <= 27) {
            BAR_ARRIVE(2);                                       // credit stage warps
        }
    }
}

// ---------------------------------------------------------------------------
__global__ __launch_bounds__(NTHREADS, 1) void fused_kernel(
    const float* __restrict__ x,
    const float* __restrict__ Wih1, const float* __restrict__ Whh1, const float* __restrict__ b1,
    const float* __restrict__ Wih2, const float* __restrict__ Whh2, const float* __restrict__ b2,
    const float* __restrict__ Wout, const float* __restrict__ bout,
    float* __restrict__ out)
{
    extern __shared__ float smem[];
    float* ring = smem;                              // [RS][TILE_T][256]
    char*  xbuf = (char*)(smem + RING_FLOATS);       // [XS][32][XROW_B]

    __shared__ __align__(8) uint64_t bars[8];
    __shared__ float h2s[32];

    const int tid = threadIdx.x;
    const int wid = tid >> 5;
    const int l   = tid & 31;
    const int bg  = blockIdx.x;

    const uint32_t bar = smem_u32(bars);

    if (tid == 0) {
        #pragma unroll
        for (int s = 0; s < XS; s++) MBAR_INIT(bar + XFULL(s), 1);   // tx-based
        MBAR_INIT(bar + XEMPTY, 8);                                  // 8 gate warps
        #pragma unroll
        for (int s = 0; s < RS; s++) {
            MBAR_INIT(bar + RFULL(s),  8);
            MBAR_INIT(bar + REMPTY(s), 2);
        }
    }
    __syncthreads();

    if (wid < 8) {
        // ===== STAGE WARPS: cp.async, EVEN tiles only ========================
        const int sj = tid;                               // 0..255
        const float4* xg = (const float4*)x;
        const size_t rowbase = (size_t)bg * 32 * 3200;
        const uint32_t xb_base = smem_u32(xbuf);

        uint32_t dsto[13];
        int      srco[13];
        #pragma unroll
        for (int m = 0; m < 13; m++) {
            int i = m * 256 + sj;
            int b = i / 100, q = i - b * 100;
            dsto[m] = (uint32_t)((b * XROW4 + q) * 16);
            srco[m] = b * 3200 + q;
        }

        #define ISSUE_TILE(K, SLOT) do {                                          \
            uint32_t dbase = xb_base + (uint32_t)(SLOT) * XSLOT_B;                \
            _Pragma("unroll")                                                     \
            for (int m = 0; m < 13; m++) {                                        \
                if (m < 12 || sj < 128)                                           \
                    CP_ASYNC16(dbase + dsto[m], xg + rowbase + srco[m] + (K) * 100); \
            }                                                                     \
            CP_COMMIT();                                                          \
        } while (0)

        ISSUE_TILE(0, 0);
        ISSUE_TILE(2, 2);
        CP_WAIT(1);                                       // tile 0 landed
        BAR_ARRIVE(1);                                    // tile 0 ready

        for (int i = 1; i <= 15; i++) {
            if (i <= 14) {
                BAR_SYNC(2);                              // slot (2i+2)%3 free (odd 2i-1 done)
                ISSUE_TILE(2 * i + 2, (2 * i + 2) % 3);
                CP_WAIT(1);                               // tile 2i landed
            } else {
                CP_WAIT(0);                               // tile 30 landed
            }
            BAR_ARRIVE(1);                                // tile 2i ready
        }
        #undef ISSUE_TILE
    } else if (wid < 16) {
        // ===== GATE WARPS ====================================================
        const int gw = wid - 8;
        const int L  = gw & 1;       // 0: LSTM1, 1: LSTM2
        const int tq = gw >> 1;      // t-quad 0..3
        if (L == 0) gate_loop<12>((const float4*)xbuf, ring, bar, l, tq, Wih1, b1);
        else        gate_loop<13>((const float4*)xbuf, ring, bar, l, tq, Wih2, b2);
    } else if (wid < 18) {
        // ===== CONSUMER: serial recurrence ===================================
        const int cw = wid - 16;     // 0: LSTM1, 1: LSTM2

        const float* Whh = cw ? Whh2 : Whh1;
        const float whi = Whh[0] * 0.5f;
        const float whf = Whh[1] * 0.5f;
        const float whg = Whh[2];
        const float who = Whh[3] * 0.5f;

        float h = 0.0f, c = 0.0f;

        for (int k = 0; k < NTILE; k++) {
            const int s = k & (RS - 1);
            mbar_wait_parity(bar + RFULL(s), (k >> 1) & 1);

            const float4* zp = (const float4*)&ring[(size_t)(s * TILE_T) * 256 + cw * 128 + l * 4];
            float4 z = zp[0];
            #pragma unroll
            for (int d = 0; d < TILE_T; d++) {
                float4 zn = z;
                if (d + 1 < TILE_T) zn = zp[(d + 1) * 64];

                float zi = fmaf(whi, h, z.x);
                float zf = fmaf(whf, h, z.y);
                float zg = fmaf(whg, h, z.z);
                float zo = fmaf(who, h, z.w);

                float gi = fmaf(0.5f, tanha(zi), 0.5f);
                float gf = fmaf(0.5f, tanha(zf), 0.5f);
                float gg = tanha(zg);
                float go = fmaf(0.5f, tanha(zo), 0.5f);

                c = fmaf(gf, c, gi * gg);
                h = go * tanha(c);
                z = zn;
            }
            __syncwarp();
            if (l == 0) MBAR_ARRIVE(bar + REMPTY(s));
        }

        if (cw == 1) h2s[l] = h;
        asm volatile("bar.sync 3, 64;" ::: "memory");
        if (cw == 0) {
            float h2 = h2s[l];
            float y = fmaf(Wout[0], h, fmaf(Wout[1], h2, bout[0]));
            out[bg * 32 + l] = 1.0f / (1.0f + __expf(-y));
        }
    } else {
        // ===== TMA WARP: bulk-copy staging of ODD tiles (elected lane) =======
        if (l == 0) {
            const char* xsrc = (const char*)x + (size_t)bg * 32 * ROW_STRIDE_B;
            const uint32_t xb_base = smem_u32(xbuf);

            for (int j = 0; j < 16; j++) {
                const int k = 2 * j + 1;
                const int slot = k % 3;
                if (j >= 1)
                    mbar_wait_parity(bar + XEMPTY, (uint32_t)((j - 1) & 1));  // even 2j-2 consumed
                MBAR_EXPECT_TX(bar + XFULL(slot), TILE_B);
                const uint32_t dslot = xb_base + (uint32_t)slot * XSLOT_B;
                const char* src = xsrc + (size_t)k * TILE_ROW_B;
                #pragma unroll 8
                for (int b = 0; b < 32; b++) {
                    CP_BULK(dslot + (uint32_t)b * XROW_B,
                            src + (size_t)b * ROW_STRIDE_B,
                            TILE_ROW_B, bar + XFULL(slot));
                }
            }
        }
    }
}

// ---------------------------------------------------------------------------
extern "C" void kernel_launch(void* const* d_in, const int* in_sizes, int n_in,
                              void* d_out, int out_size)
{
    const float* x    = (const float*)d_in[0];
    const float* Wih1 = (const float*)d_in[1];
    const float* Whh1 = (const float*)d_in[2];
    const float* b1   = (const float*)d_in[3];
    const float* Wih2 = (const float*)d_in[4];
    const float* Whh2 = (const float*)d_in[5];
    const float* b2   = (const float*)d_in[6];
    const float* Wout = (const float*)d_in[7];
    const float* bout = (const float*)d_in[8];

    cudaFuncSetAttribute(fused_kernel, cudaFuncAttributeMaxDynamicSharedMemorySize, SMEM_BYTES);
    fused_kernel<<<NGRP, NTHREADS, SMEM_BYTES>>>(
        x, Wih1, Whh1, b1, Wih2, Whh2, b2, Wout, bout, (float*)d_out);
}

// round 15
// speedup vs baseline: 2.0539x; 1.0617x over previous
#include <cuda_runtime.h>
#include <cstdint>

#define NGRID   148          // one CTA per SM (safe floor for GB300)
#define B_TOT   4096
#define T_TOT   512
#define TILE_T  16
#define NTILE   32
#define XS      3            // xbuf slots (cp.async triple buffer)
#define RS      2            // gate-ring slots
#define PROD_T  512
#define CONS_T  64
#define NTHREADS 576

#define XROW4       104                      // float4 per xbuf row (100 data + pad, mult of 8)
#define XSLOT_F4    (32 * XROW4)             // 3328 float4 per slot
#define RING_FLOATS (RS * TILE_T * 256)      // 8192 floats = 32 KB
#define SMEM_BYTES  (RING_FLOATS * 4 + XS * XSLOT_F4 * 16)   // 192.5 KB

__device__ __forceinline__ float tanha(float v) {
    float y;
    asm("tanh.approx.f32 %0, %1;" : "=f"(y) : "f"(v));
    return y;
}

__device__ __forceinline__ uint32_t smem_u32(const void* p) {
    uint32_t a;
    asm("{ .reg .u64 t; cvta.to.shared.u64 t, %1; cvt.u32.u64 %0, t; }" : "=r"(a) : "l"(p));
    return a;
}

#define MBAR_INIT(addr, cnt) \
    asm volatile("mbarrier.init.shared.b64 [%0], %1;" :: "r"(addr), "r"(cnt) : "memory")
#define MBAR_ARRIVE(addr) \
    asm volatile("mbarrier.arrive.release.cta.shared::cta.b64 _, [%0];" :: "r"(addr) : "memory")

__device__ __forceinline__ void mbar_wait_parity(uint32_t mbar, uint32_t parity) {
    uint32_t done;
    asm volatile(
        "{\n\t.reg .pred p;\n\t"
        "mbarrier.try_wait.parity.acquire.cta.shared::cta.b64 p, [%1], %2;\n\t"
        "selp.b32 %0, 1, 0, p;\n\t}"
        : "=r"(done) : "r"(mbar), "r"(parity) : "memory");
    if (!done) {
        asm volatile(
            "{\n\t.reg .pred P1;\n\t"
            "W_%=:\n\t"
            "mbarrier.try_wait.parity.acquire.cta.shared::cta.b64 P1, [%0], %1, 0x989680;\n\t"
            "@P1 bra.uni D_%=;\n\t"
            "bra.uni W_%=;\n\t"
            "D_%=:\n\t}"
            :: "r"(mbar), "r"(parity) : "memory");
    }
}

#define CP_ASYNC16(dst_u32, src_ptr) \
    asm volatile("cp.async.cg.shared.global [%0], [%1], 16;" \
                 :: "r"(dst_u32), "l"(src_ptr) : "memory")
#define CP_COMMIT()  asm volatile("cp.async.commit_group;" ::: "memory")
#define CP_WAIT(N)   asm volatile("cp.async.wait_group %0;" :: "n"(N) : "memory")

#define BAR_SYNC(id)   asm volatile("bar.sync %0, %1;"   :: "n"(id), "n"(PROD_T) : "memory")
#define BAR_ARRIVE(id) asm volatile("bar.arrive %0, %1;" :: "n"(id), "n"(PROD_T) : "memory")

// ---------------------------------------------------------------------------
// Gate warps: one warp per (LSTM L, t-quad tq). lane = batch-in-group; thread
// computes 4 timesteps x 4 gates from swizzled xbuf; writes float4 to ring.
// Lanes >= cnt compute garbage from allocated smem (harmless, discarded).
// ---------------------------------------------------------------------------
template <int NF>
__device__ __forceinline__ void gate_loop(
    const float4* __restrict__ xb4, float* __restrict__ ring,
    uint32_t full_base, uint32_t empty_base,
    int l, int tq, const float* __restrict__ Wih, const float* __restrict__ bp)
{
    constexpr int FOFF = (NF == 13) ? 12 : 0;
    constexpr int LOFF = (NF == 13) ? 128 : 0;

    float w[4][13], bb[4];
    #pragma unroll
    for (int g = 0; g < 4; g++) {
        float sc = (g == 2) ? 1.0f : 0.5f;
        bb[g] = bp[g] * sc;
        #pragma unroll
        for (int f = 0; f < NF; f++) w[g][f] = Wih[g * NF + f] * sc;
    }

    const int xl  = l & 7;
    const int tq4 = tq * 4;

    BAR_ARRIVE(2);                 // initial slot-reuse credit for stage iter 0

    int xs = 0;                    // xbuf slot = k % 3
    for (int k = 0; k < NTILE; k++) {
        BAR_SYNC(1);               // tile k landed
        const int s = k & (RS - 1);
        mbar_wait_parity(empty_base + s * 8, 1u ^ ((k >> 1) & 1));

        const float4* xr = xb4 + (size_t)(xs * 32 + l) * XROW4;

        #pragma unroll
        for (int i = 0; i < 4; i++) {
            const int tloc = tq4 + i;
            const int q0 = (tloc * 25 + FOFF) >> 2;   // window start; offset == i
            const int nq = (i + NF + 3) >> 2;

            float xa[16];
            #pragma unroll
            for (int j = 0; j < 4; j++) {
                if (j < nq) {
                    float4 t = xr[(q0 + j) ^ xl];
                    xa[4 * j + 0] = t.x; xa[4 * j + 1] = t.y;
                    xa[4 * j + 2] = t.z; xa[4 * j + 3] = t.w;
                }
            }

            float a0 = bb[0], a1 = bb[1], a2 = bb[2], a3 = bb[3];
            #pragma unroll
            for (int f = 0; f < NF; f++) {
                float v = xa[i + f];
                a0 = fmaf(w[0][f], v, a0);
                a1 = fmaf(w[1][f], v, a1);
                a2 = fmaf(w[2][f], v, a2);
                a3 = fmaf(w[3][f], v, a3);
            }

            *(float4*)(ring + (size_t)(s * TILE_T + tloc) * 256 + LOFF + l * 4) =
                make_float4(a0, a1, a2, a3);
        }

        __syncwarp();
        if (l == 0) MBAR_ARRIVE(full_base + s * 8);   // ring slot filled (elected)
        if (k < NTILE - 1) BAR_ARRIVE(2);             // slot k%3 free for reuse
        if (++xs == XS) xs = 0;
    }
}

// ---------------------------------------------------------------------------
__global__ __launch_bounds__(NTHREADS, 1) void fused_kernel(
    const float* __restrict__ x,
    const float* __restrict__ Wih1, const float* __restrict__ Whh1, const float* __restrict__ b1,
    const float* __restrict__ Wih2, const float* __restrict__ Whh2, const float* __restrict__ b2,
    const float* __restrict__ Wout, const float* __restrict__ bout,
    float* __restrict__ out)
{
    extern __shared__ float smem[];
    float*  ring = smem;                             // [RS][TILE_T][256]
    float4* xb4  = (float4*)(smem + RING_FLOATS);    // [XS][32][XROW4]

    __shared__ __align__(8) uint64_t bars[2 * RS];
    __shared__ float h2s[32];

    const int tid = threadIdx.x;
    const int wid = tid >> 5;
    const int bg  = blockIdx.x;

    // balanced batch split over NGRID CTAs: cnt in {27, 28}
    const int start = (bg * B_TOT) / NGRID;
    const int cnt   = ((bg + 1) * B_TOT) / NGRID - start;

    const uint32_t full_base  = smem_u32(bars);
    const uint32_t empty_base = full_base + RS * 8;

    if (tid == 0) {
        #pragma unroll
        for (int s = 0; s < RS; s++) {
            MBAR_INIT(full_base  + s * 8, 8);        // 8 gate warps (elected)
            MBAR_INIT(empty_base + s * 8, 2);        // 2 consumer warps (elected)
        }
    }
    __syncthreads();

    if (wid < 8) {
        // ===== STAGE WARPS: cp.async GMEM -> swizzled SMEM (cnt rows) =========
        const int sj = tid;                               // 0..255
        const float4* xg = (const float4*)x;
        const size_t rowbase = (size_t)start * 3200;      // f4 per batch row
        const uint32_t xb_base = smem_u32(xb4);
        const int tot = cnt * 100;                        // valid f4 per tile

        uint32_t dsto[11];
        int      srco[11];
        bool     val[11];
        #pragma unroll
        for (int m = 0; m < 11; m++) {
            int i = m * 256 + sj;
            val[m] = (i < tot);
            int b = i / 100, q = i - b * 100;
            dsto[m] = (uint32_t)((b * XROW4 + (q ^ (b & 7))) * 16);
            srco[m] = b * 3200 + q;
        }

        #define ISSUE_TILE(K, SLOT) do {                                          \
            uint32_t dbase = xb_base + (uint32_t)(SLOT) * (XSLOT_F4 * 16);        \
            _Pragma("unroll")                                                     \
            for (int m = 0; m < 11; m++) {                                        \
                if (val[m])                                                       \
                    CP_ASYNC16(dbase + dsto[m], xg + rowbase + srco[m] + (K) * 100); \
            }                                                                     \
        } while (0)

        ISSUE_TILE(0, 0); CP_COMMIT();
        ISSUE_TILE(1, 1); CP_COMMIT();
        CP_WAIT(1);                                       // tile 0 landed
        BAR_ARRIVE(1);                                    // signal tile 0 ready

        int slot = 2;                                     // slot for tile k+2
        for (int k = 0; k < NTILE; k++) {
            BAR_SYNC(2);                                  // gates done with tile k-1
            if (k + 2 < NTILE) ISSUE_TILE(k + 2, slot);
            CP_COMMIT();                                  // uniform group accounting
            if (k + 1 < NTILE) {
                CP_WAIT(1);                               // tile k+1 landed
                BAR_ARRIVE(1);                            // signal tile k+1 ready
            }
            if (++slot == XS) slot = 0;
        }
        #undef ISSUE_TILE
    } else if (wid < 16) {
        // ===== GATE WARPS ====================================================
        const int gw = wid - 8;
        const int L  = gw & 1;       // 0: LSTM1, 1: LSTM2
        const int tq = gw >> 1;      // t-quad 0..3
        const int l  = tid & 31;     // batch lane
        if (L == 0) gate_loop<12>(xb4, ring, full_base, empty_base, l, tq, Wih1, b1);
        else        gate_loop<13>(xb4, ring, full_base, empty_base, l, tq, Wih2, b2);
    } else {
        // ===== CONSUMER: serial recurrence ===================================
        const int ctid = tid - PROD_T;
        const int cw   = ctid >> 5;  // 0: LSTM1, 1: LSTM2
        const int lane = ctid & 31;

        const float* Whh = cw ? Whh2 : Whh1;
        const float whi = Whh[0] * 0.5f;
        const float whf = Whh[1] * 0.5f;
        const float whg = Whh[2];
        const float who = Whh[3] * 0.5f;

        float h = 0.0f, c = 0.0f;

        for (int k = 0; k < NTILE; k++) {
            const int s = k & (RS - 1);
            mbar_wait_parity(full_base + s * 8, (k >> 1) & 1);

            const float4* zp = (const float4*)&ring[(size_t)(s * TILE_T) * 256 + cw * 128 + lane * 4];
            float4 z = zp[0];
            #pragma unroll
            for (int d = 0; d < TILE_T; d++) {
                float4 zn = z;
                if (d + 1 < TILE_T) zn = zp[(d + 1) * 64];

                float zi = fmaf(whi, h, z.x);
                float zf = fmaf(whf, h, z.y);
                float zg = fmaf(whg, h, z.z);
                float zo = fmaf(who, h, z.w);

                float gi = fmaf(0.5f, tanha(zi), 0.5f);
                float gf = fmaf(0.5f, tanha(zf), 0.5f);
                float gg = tanha(zg);
                float go = fmaf(0.5f, tanha(zo), 0.5f);

                c = fmaf(gf, c, gi * gg);
                h = go * tanha(c);
                z = zn;
            }
            __syncwarp();
            if (lane == 0) MBAR_ARRIVE(empty_base + s * 8);
        }

        if (cw == 1) h2s[lane] = h;
        asm volatile("bar.sync 3, %0;" :: "n"(CONS_T) : "memory");
        if (cw == 0 && lane < cnt) {
            float h2 = h2s[lane];
            float y = fmaf(Wout[0], h, fmaf(Wout[1], h2, bout[0]));
            out[start + lane] = 1.0f / (1.0f + __expf(-y));
        }
    }
}

// ---------------------------------------------------------------------------
extern "C" void kernel_launch(void* const* d_in, const int* in_sizes, int n_in,
                              void* d_out, int out_size)
{
    const float* x    = (const float*)d_in[0];
    const float* Wih1 = (const float*)d_in[1];
    const float* Whh1 = (const float*)d_in[2];
    const float* b1   = (const float*)d_in[3];
    const float* Wih2 = (const float*)d_in[4];
    const float* Whh2 = (const float*)d_in[5];
    const float* b2   = (const float*)d_in[6];
    const float* Wout = (const float*)d_in[7];
    const float* bout = (const float*)d_in[8];

    cudaFuncSetAttribute(fused_kernel, cudaFuncAttributeMaxDynamicSharedMemorySize, SMEM_BYTES);
    fused_kernel<<<NGRID, NTHREADS, SMEM_BYTES>>>(
        x, Wih1, Whh1, b1, Wih2, Whh2, b2, Wout, bout, (float*)d_out);
}